// round 17
// baseline (speedup 1.0000x reference)
#include <cuda_runtime.h>
#include <math.h>

#define B 128

__device__ float g_h1[B * 1024];
__device__ float g_h2[B * 512];
__device__ float g_h3[B * 256];
__device__ float g_aw1[512 * 1024];   // pre-clamped W1 (written in L0 prologue)
__device__ float g_aw2[256 * 512];    // pre-clamped W2
__device__ float g_aw3[128 * 256];    // pre-clamped W3

__device__ __forceinline__ float ex2f(float x) {
    float y;
    asm("ex2.approx.f32 %0, %1;" : "=f"(y) : "f"(x));
    return y;
}

// identity on [0,1], slope 0.1 outside
__device__ __forceinline__ float leaky_clamp01(float w) {
    float r = w;
    if (w < 0.0f)      r = 0.1f * w;
    else if (w > 1.0f) r = 1.0f + 0.1f * (w - 1.0f);
    return r;
}

__device__ __forceinline__ float tau_scale(const float* taup, float tau_floor) {
    float ta  = __ldg(taup);
    float tau = tau_floor + (ta >= 0.0f ? ta : 0.05f * ta);  // leaky_relu
    return tau * 1.4426950408889634f;                        // tau * log2(e)
}

#define EXP_UPD(zz, nn, dd) { float e = ex2f(zz); dd += e; nn = fmaf(e, (zz), nn); }

// ============================================================================
// 2x2 micro-tile chunked kernel (big layers). Thread owns batches {bq, bq+BT/2}
// x outputs {oq, oq+OT/2}: 2 c-loads + 2 a-loads feed 16 exps -> 4 smem B/exp
// (half the crossbar at MUFU saturation) and ~4.25 issue slots/exp.
// S-way K split restores warp count; (num,den) partials reduced via smem.
// PRE (L0): prologue pre-clamps W1/W2/W3 into g_aw*. CLAMPED: copy-only staging.
// CAT: layer-0 mode, h is x[B][IN/2], staged as concat(x, 1-x).
// ============================================================================
template <int IN, int BT, int OT, int KC, int S, bool CAT, bool PRE, bool CLAMPED>
__global__ __launch_bounds__((BT / 2) * (OT / 2) * S) void layer_tile(
    const float* __restrict__ h, const float* __restrict__ W,
    const float* __restrict__ taup, float tau_floor,
    float* __restrict__ out, int out_dim,
    const float* __restrict__ Wp1, const float* __restrict__ Wp2,
    const float* __restrict__ Wp3) {
    constexpr int BH  = BT / 2;
    constexpr int OH  = OT / 2;
    constexpr int G   = BH * OH;
    constexpr int T   = G * S;
    constexpr int KR  = KC / S;
    constexpr int KCP = KC + 4;
    __shared__ float  ch[BT * KCP];
    __shared__ float  aw[OT * KCP];
    __shared__ float4 rnum[S > 1 ? T : 1];
    __shared__ float4 rden[S > 1 ? T : 1];

    const int tid   = threadIdx.x;
    const int obase = blockIdx.x * OT;
    const int bbase = blockIdx.y * BT;
    const int idx   = tid % G;
    const int s     = tid / G;
    const int bq    = idx % BH;
    const int oq    = idx / BH;

    if (PRE) {
        // pre-clamp W1 (131072 f4) + W2 (32768 f4) + W3 (8192 f4)
        const int NT = gridDim.x * gridDim.y * T;
        int gid = (blockIdx.y * gridDim.x + blockIdx.x) * T + tid;
        for (int g = gid; g < 172032; g += NT) {
            const float4* src;
            float4* dst;
            if (g < 131072)      { src = (const float4*)Wp1 + g;            dst = (float4*)g_aw1 + g; }
            else if (g < 163840) { src = (const float4*)Wp2 + (g - 131072); dst = (float4*)g_aw2 + (g - 131072); }
            else                 { src = (const float4*)Wp3 + (g - 163840); dst = (float4*)g_aw3 + (g - 163840); }
            float4 v = *src, r;
            r.x = leaky_clamp01(v.x); r.y = leaky_clamp01(v.y);
            r.z = leaky_clamp01(v.z); r.w = leaky_clamp01(v.w);
            *dst = r;
        }
    }

    const float cs = tau_scale(taup, tau_floor);

    float n00 = 0.f, n01 = 0.f, n10 = 0.f, n11 = 0.f;
    float d00 = 0.f, d01 = 0.f, d10 = 0.f, d11 = 0.f;

    for (int k0 = 0; k0 < IN; k0 += KC) {
        if (k0) __syncthreads();
        {   // stage activations (fused concat(x,1-x) for layer 0)
            const bool inv  = CAT && (k0 >= IN / 2);
            const float sc  = inv ? -cs : cs;
            const float off = inv ?  cs : 0.0f;
            const int hk0   = CAT ? (k0 & (IN / 2 - 1)) : k0;
            const int hstr  = CAT ? (IN / 2) : IN;
            #pragma unroll
            for (int i = tid; i < BT * (KC / 4); i += T) {
                int bb = i / (KC / 4), kv = i - bb * (KC / 4);
                float4 v = *(const float4*)&h[(bbase + bb) * hstr + hk0 + kv * 4];
                float4 r;
                r.x = fmaf(v.x, sc, off); r.y = fmaf(v.y, sc, off);
                r.z = fmaf(v.z, sc, off); r.w = fmaf(v.w, sc, off);
                *(float4*)&ch[bb * KCP + kv * 4] = r;
            }
        }
        #pragma unroll
        for (int i = tid; i < OT * (KC / 4); i += T) {
            int oo = i / (KC / 4), kv = i - oo * (KC / 4);
            float4 v = *(const float4*)&W[(obase + oo) * IN + k0 + kv * 4];
            if (!CLAMPED) {
                float4 r;
                r.x = leaky_clamp01(v.x); r.y = leaky_clamp01(v.y);
                r.z = leaky_clamp01(v.z); r.w = leaky_clamp01(v.w);
                *(float4*)&aw[oo * KCP + kv * 4] = r;
            } else {
                *(float4*)&aw[oo * KCP + kv * 4] = v;
            }
        }
        __syncthreads();

        const float* cp0 = &ch[bq * KCP + s * KR];
        const float* cp1 = &ch[(bq + BH) * KCP + s * KR];
        const float* ap0 = &aw[oq * KCP + s * KR];
        const float* ap1 = &aw[(oq + OH) * KCP + s * KR];
        #pragma unroll 4
        for (int k = 0; k < KR; k += 4) {
            float4 c0 = *(const float4*)&cp0[k];
            float4 c1 = *(const float4*)&cp1[k];
            float4 a0 = *(const float4*)&ap0[k];
            float4 a1 = *(const float4*)&ap1[k];
            float z;
            z = c0.x * a0.x; EXP_UPD(z, n00, d00);
            z = c0.y * a0.y; EXP_UPD(z, n00, d00);
            z = c0.z * a0.z; EXP_UPD(z, n00, d00);
            z = c0.w * a0.w; EXP_UPD(z, n00, d00);
            z = c0.x * a1.x; EXP_UPD(z, n01, d01);
            z = c0.y * a1.y; EXP_UPD(z, n01, d01);
            z = c0.z * a1.z; EXP_UPD(z, n01, d01);
            z = c0.w * a1.w; EXP_UPD(z, n01, d01);
            z = c1.x * a0.x; EXP_UPD(z, n10, d10);
            z = c1.y * a0.y; EXP_UPD(z, n10, d10);
            z = c1.z * a0.z; EXP_UPD(z, n10, d10);
            z = c1.w * a0.w; EXP_UPD(z, n10, d10);
            z = c1.x * a1.x; EXP_UPD(z, n11, d11);
            z = c1.y * a1.y; EXP_UPD(z, n11, d11);
            z = c1.z * a1.z; EXP_UPD(z, n11, d11);
            z = c1.w * a1.w; EXP_UPD(z, n11, d11);
        }
    }

    if (S > 1) {
        rnum[tid] = make_float4(n00, n01, n10, n11);
        rden[tid] = make_float4(d00, d01, d10, d11);
        __syncthreads();
        if (s) return;
        #pragma unroll
        for (int ss = 1; ss < S; ss++) {
            float4 pn = rnum[idx + ss * G];
            float4 pd = rden[idx + ss * G];
            n00 += pn.x; n01 += pn.y; n10 += pn.z; n11 += pn.w;
            d00 += pd.x; d01 += pd.y; d10 += pd.z; d11 += pd.w;
        }
    }

    const float invc = 1.0f / cs;
    const int b0 = bbase + bq, b1 = b0 + BH;
    const int o0 = obase + oq, o1 = o0 + OH;
    out[b0 * out_dim + o0] = 1.0f - (n00 / d00) * invc;
    out[b0 * out_dim + o1] = 1.0f - (n01 / d01) * invc;
    out[b1 * out_dim + o0] = 1.0f - (n10 / d10) * invc;
    out[b1 * out_dim + o1] = 1.0f - (n11 / d11) * invc;
}

// ============================================================================
// Split kernel (small layers, R16-proven). Whole input staged once; S threads
// per output, each covering IN/S of K; partials reduced via smem. Weights
// come pre-clamped (pure copy staging).
// ============================================================================
template <int IN, int BT, int OT, int S>
__global__ __launch_bounds__(BT * OT * S) void layer_split(
    const float* __restrict__ h, const float* __restrict__ W,
    const float* __restrict__ taup, float tau_floor,
    float* __restrict__ out, int out_dim) {
    constexpr int T   = BT * OT * S;
    constexpr int G   = BT * OT;
    constexpr int KR  = IN / S;
    constexpr int INP = IN + 4;
    __shared__ float ch[BT * INP];
    __shared__ float aw[OT * INP];
    __shared__ float2 rpart[T];

    const int tid   = threadIdx.x;
    const int obase = blockIdx.x * OT;
    const int bbase = blockIdx.y * BT;
    const int idx   = tid & (G - 1);
    const int s     = tid / G;
    const int b     = idx % BT;
    const int o     = idx / BT;

    const float cs = tau_scale(taup, tau_floor);

    #pragma unroll
    for (int i = tid; i < BT * (IN / 4); i += T) {
        int bb = i / (IN / 4), kv = i - bb * (IN / 4);
        float4 v = *(const float4*)&h[(bbase + bb) * IN + kv * 4];
        float4 r; r.x = v.x * cs; r.y = v.y * cs; r.z = v.z * cs; r.w = v.w * cs;
        *(float4*)&ch[bb * INP + kv * 4] = r;
    }
    #pragma unroll
    for (int i = tid; i < OT * (IN / 4); i += T) {
        int oo = i / (IN / 4), kv = i - oo * (IN / 4);
        *(float4*)&aw[oo * INP + kv * 4] =
            *(const float4*)&W[(obase + oo) * IN + kv * 4];   // pre-clamped
    }
    __syncthreads();

    float num = 0.0f, den = 0.0f;
    const float* cp = &ch[b * INP + s * KR];
    const float* ap = &aw[o * INP + s * KR];
    #pragma unroll 4
    for (int k = 0; k < KR; k += 4) {
        float4 c = *(const float4*)&cp[k];
        float4 a = *(const float4*)&ap[k];
        float z;
        z = c.x * a.x; EXP_UPD(z, num, den);
        z = c.y * a.y; EXP_UPD(z, num, den);
        z = c.z * a.z; EXP_UPD(z, num, den);
        z = c.w * a.w; EXP_UPD(z, num, den);
    }

    rpart[tid] = make_float2(num, den);
    __syncthreads();
    if (s == 0) {
        #pragma unroll
        for (int ss = 1; ss < S; ss++) {
            float2 p = rpart[idx + ss * G];
            num += p.x;
            den += p.y;
        }
        out[(bbase + b) * out_dim + obase + o] = 1.0f - (num / den) / cs;
    }
}

extern "C" void kernel_launch(void* const* d_in, const int* in_sizes, int n_in,
                              void* d_out, int out_size) {
    // metadata order: x, W0, tau0, W1, tau1, W2, tau2, W3, tau3
    const float* x  = (const float*)d_in[0];
    const float* W0 = (const float*)d_in[1];
    const float* t0 = (const float*)d_in[2];
    const float* W1 = (const float*)d_in[3];
    const float* t1 = (const float*)d_in[4];
    const float* W2 = (const float*)d_in[5];
    const float* t2 = (const float*)d_in[6];
    const float* W3 = (const float*)d_in[7];
    const float* t3 = (const float*)d_in[8];
    float* out = (float*)d_out;

    float *h1, *h2, *h3, *aw1, *aw2, *aw3;
    cudaGetSymbolAddress((void**)&h1, g_h1);
    cudaGetSymbolAddress((void**)&h2, g_h2);
    cudaGetSymbolAddress((void**)&h3, g_h3);
    cudaGetSymbolAddress((void**)&aw1, g_aw1);
    cudaGetSymbolAddress((void**)&aw2, g_aw2);
    cudaGetSymbolAddress((void**)&aw3, g_aw3);

    // tau_floor = log(in-1) + log(0.95/0.05)
    const float L19 = 2.9444389791664403f;
    const float tf0 = logf(1023.0f) + L19;
    const float tf1 = logf(1023.0f) + L19;
    const float tf2 = logf(511.0f)  + L19;
    const float tf3 = logf(255.0f)  + L19;

    // L0: 1024->1024, 2x2 tile, S=2, fused concat + pre-clamp of W1/W2/W3.
    // 512 blocks x 128 thr, smem ~44KB -> ~5 CTA/SM.
    layer_tile<1024, 8, 32, 256, 2, true, true, false>
        <<<dim3(1024 / 32, B / 8), 128>>>(x, W0, t0, tf0, h1, 1024, W1, W2, W3);
    // L1: 1024->512, 2x2 tile, S=4, pre-clamped weights. 512 blocks x 128 thr.
    layer_tile<1024, 8, 16, 256, 4, false, false, true>
        <<<dim3(512 / 16, B / 8), 128>>>(h1, aw1, t1, tf1, h2, 512,
                                         nullptr, nullptr, nullptr);
    // L2: 512->256, 4-way split, pre-clamped. 512 blocks x 256 thr.
    layer_split<512, 8, 8, 4>
        <<<dim3(256 / 8, B / 8), 256>>>(h2, aw2, t2, tf2, h3, 256);
    // L3: 256->128, 4-way split, pre-clamped. 256 blocks x 256 thr.
    layer_split<256, 8, 8, 4>
        <<<dim3(128 / 8, B / 8), 256>>>(h3, aw3, t3, tf3, out, 128);
}